// round 4
// baseline (speedup 1.0000x reference)
#include <cuda_runtime.h>

#define NB 32
#define HIDDEN 256
#define NQH 4
#define NKVH 2
#define HD 64
#define QKV_DIM 512
#define MAXS 8192
#define CHUNK 512
#define NCHUNK (MAXS / CHUNK)          // 16
#define NHEAD (NB * NQH)               // 128
#define NQKV_CTA (NB * 2)              // 64 qkv CTAs
#define NWORK (NB * NKVH * NCHUNK)     // 1024 worker CTAs

// ---------------- scratch (device globals) ----------------------------------
__device__ float g_q[NB * HIDDEN];
__device__ float g_k[NB * NKVH * HD];
__device__ float g_v[NB * NKVH * HD];
__device__ float g_pm[NHEAD * NCHUNK];
__device__ float g_pl[NHEAD * NCHUNK];
__device__ float g_pa[NHEAD * NCHUNK * HD];
__device__ int   g_ready[NB];          // zero-init; reset by finisher
__device__ int   g_cnt[NB];            // zero-init; reset by finisher

// ---------------- the single fused kernel ------------------------------------
__global__ void __launch_bounds__(256) mega_kernel(
    const float* __restrict__ x, const float* __restrict__ kv,
    const int* __restrict__ ctx_len, const float* __restrict__ rope,
    const float* __restrict__ qkv_w, const float* __restrict__ qkv_b,
    const float* __restrict__ out_w, float* __restrict__ out)
{
    int blk = blockIdx.x;
    int t   = threadIdx.x;

    // ================= role 1: qkv projection + rope (blocks 0..63) =========
    if (blk < NQKV_CTA) {
        int b = blk >> 1, half = blk & 1;
        __shared__ float sx[HIDDEN];
        __shared__ float sq[256];
        sx[t] = x[b * HIDDEN + t];
        __syncthreads();

        int e = half * 256 + t;
        const float4* w4 = (const float4*)(qkv_w + (size_t)e * HIDDEN);
        float s = qkv_b[e];
#pragma unroll
        for (int j = 0; j < HIDDEN / 4; j++) {
            float4 w = w4[j];
            s += w.x * sx[4 * j] + w.y * sx[4 * j + 1]
               + w.z * sx[4 * j + 2] + w.w * sx[4 * j + 3];
        }
        sq[t] = s;
        __syncthreads();

        int pos = ctx_len[b];
        const float* cs = rope + (size_t)pos * HD;   // [0:32)=cos, [32:64)=sin
        int d = t & 63, base = t & ~63;
        float val;
        if (half == 0 || t < 128) {   // q or k: rope
            if (d < 32)
                val = sq[base + d] * cs[d] - sq[base + d + 32] * cs[d + 32];
            else
                val = sq[base + d - 32] * cs[d] + sq[base + d] * cs[d - 32];
        } else {
            val = sq[t];              // v: no rope
        }
        if (half == 0)      g_q[b * HIDDEN + t] = val;
        else if (t < 128)   g_k[b * NKVH * HD + t] = val;
        else                g_v[b * NKVH * HD + (t - 128)] = val;

        __threadfence();
        __syncthreads();
        if (t == 0) atomicAdd(&g_ready[b], 1);
        return;
    }

    // ================= role 2: fused cache copy + flash-decode ==============
    int wblk  = blk - NQKV_CTA;
    int chunk = wblk & (NCHUNK - 1);
    int h     = (wblk >> 4) & (NKVH - 1);
    int b     = wblk >> 5;
    int warp  = t >> 5, lane = t & 31;
    int half  = lane >> 4, li = lane & 15;
    int pos   = ctx_len[b];

    size_t kb = (((size_t)b * 2 + 0) * NKVH + h) * (size_t)(MAXS * HD);
    size_t vb = kb + (size_t)NKVH * MAXS * HD;
    const float4* kp4 = (const float4*)(kv + kb);
    const float4* vp4 = (const float4*)(kv + vb);
    float4* okp4 = (float4*)(out + NB * HIDDEN + kb);
    float4* ovp4 = (float4*)(out + NB * HIDDEN + vb);

    // wait for this batch's qkv (both halves published)
    if (t == 0) {
        while (*(volatile int*)&g_ready[b] != 2) __nanosleep(64);
    }
    __syncthreads();

    int hq = h * 2;
    int d4 = li * 4;
    float4 q0 = *(const float4*)&g_q[((size_t)b * NQH + hq)     * HD + d4];
    float4 q1 = *(const float4*)&g_q[((size_t)b * NQH + hq + 1) * HD + d4];
    float4 kn = *(const float4*)&g_k[((size_t)b * NKVH + h) * HD + d4];
    float4 vn = *(const float4*)&g_v[((size_t)b * NKVH + h) * HD + d4];

    float m0 = -1e30f, l0 = 0.f, m1 = -1e30f, l1 = 0.f;
    float4 a0 = make_float4(0.f, 0.f, 0.f, 0.f);
    float4 a1 = make_float4(0.f, 0.f, 0.f, 0.f);
    const float scale = 0.125f;   // 64^-0.5

    int row0 = chunk * CHUNK + warp * (CHUNK / 8);
#pragma unroll 8
    for (int i = 0; i < CHUNK / 16; i++) {          // 2 rows per iter
        int m = row0 + 2 * i + half;                // per-half row
        size_t o4 = (size_t)m * (HD / 4) + li;
        float4 kd, vd;
        if (m == pos) { kd = kn; vd = vn; }
        else          { kd = __ldcs(kp4 + o4); vd = __ldcs(vp4 + o4); }
        __stcs(okp4 + o4, kd);
        __stcs(ovp4 + o4, vd);

        if (row0 + 2 * i <= pos) {                  // warp-uniform guard
            float p0 = kd.x * q0.x + kd.y * q0.y + kd.z * q0.z + kd.w * q0.w;
            float p1 = kd.x * q1.x + kd.y * q1.y + kd.z * q1.z + kd.w * q1.w;
#pragma unroll
            for (int sft = 8; sft > 0; sft >>= 1) { // stays within 16-lane half
                p0 += __shfl_xor_sync(0xffffffffu, p0, sft);
                p1 += __shfl_xor_sync(0xffffffffu, p1, sft);
            }
            if (m <= pos) {                          // per-half, ALU only
                p0 *= scale; p1 *= scale;
                float nm0 = fmaxf(m0, p0), nm1 = fmaxf(m1, p1);
                float f0 = __expf(m0 - nm0), w0 = __expf(p0 - nm0);
                float f1 = __expf(m1 - nm1), w1 = __expf(p1 - nm1);
                l0 = l0 * f0 + w0;  l1 = l1 * f1 + w1;
                a0.x = a0.x * f0 + w0 * vd.x;  a0.y = a0.y * f0 + w0 * vd.y;
                a0.z = a0.z * f0 + w0 * vd.z;  a0.w = a0.w * f0 + w0 * vd.w;
                a1.x = a1.x * f1 + w1 * vd.x;  a1.y = a1.y * f1 + w1 * vd.y;
                a1.z = a1.z * f1 + w1 * vd.z;  a1.w = a1.w * f1 + w1 * vd.w;
                m0 = nm0; m1 = nm1;
            }
        }
    }

    // merge the two half-warp softmax streams per head (shfl_xor 16)
    {
        float mo = __shfl_xor_sync(0xffffffffu, m0, 16);
        float lo = __shfl_xor_sync(0xffffffffu, l0, 16);
        float4 ao;
        ao.x = __shfl_xor_sync(0xffffffffu, a0.x, 16);
        ao.y = __shfl_xor_sync(0xffffffffu, a0.y, 16);
        ao.z = __shfl_xor_sync(0xffffffffu, a0.z, 16);
        ao.w = __shfl_xor_sync(0xffffffffu, a0.w, 16);
        float M = fmaxf(m0, mo);
        float e0 = __expf(m0 - M), e1 = __expf(mo - M);
        l0 = l0 * e0 + lo * e1;
        a0.x = a0.x * e0 + ao.x * e1;  a0.y = a0.y * e0 + ao.y * e1;
        a0.z = a0.z * e0 + ao.z * e1;  a0.w = a0.w * e0 + ao.w * e1;
        m0 = M;
    }
    {
        float mo = __shfl_xor_sync(0xffffffffu, m1, 16);
        float lo = __shfl_xor_sync(0xffffffffu, l1, 16);
        float4 ao;
        ao.x = __shfl_xor_sync(0xffffffffu, a1.x, 16);
        ao.y = __shfl_xor_sync(0xffffffffu, a1.y, 16);
        ao.z = __shfl_xor_sync(0xffffffffu, a1.z, 16);
        ao.w = __shfl_xor_sync(0xffffffffu, a1.w, 16);
        float M = fmaxf(m1, mo);
        float e0 = __expf(m1 - M), e1 = __expf(mo - M);
        l1 = l1 * e0 + lo * e1;
        a1.x = a1.x * e0 + ao.x * e1;  a1.y = a1.y * e0 + ao.y * e1;
        a1.z = a1.z * e0 + ao.z * e1;  a1.w = a1.w * e0 + ao.w * e1;
        m1 = M;
    }

    // cross-warp combine -> per-CTA partial
    __shared__ float sm[2][8], sl[2][8], sa[2][8][HD];
    __shared__ float sc[HIDDEN];
    __shared__ int s_last;
    if (lane == 0) { sm[0][warp] = m0; sl[0][warp] = l0; sm[1][warp] = m1; sl[1][warp] = l1; }
    if (half == 0) {
        *(float4*)&sa[0][warp][d4] = a0;
        *(float4*)&sa[1][warp][d4] = a1;
    }
    __syncthreads();

    if (t < 128) {
        int g = t >> 6, d = t & 63;
        float M = -1e30f;
#pragma unroll
        for (int w = 0; w < 8; w++) M = fmaxf(M, sm[g][w]);
        float L = 0.f, A = 0.f;
#pragma unroll
        for (int w = 0; w < 8; w++) {
            float e = __expf(sm[g][w] - M);
            L += sl[g][w] * e;
            A += sa[g][w][d] * e;
        }
        int head = (b * NKVH + h) * 2 + g;
        int pi = head * NCHUNK + chunk;
        if (d == 0) { g_pm[pi] = M; g_pl[pi] = L; }
        g_pa[(size_t)pi * HD + d] = A;
    }

    // ============ role 3: last CTA of batch b does combine + outproj ========
    __threadfence();
    __syncthreads();
    if (t == 0) {
        int old = atomicAdd(&g_cnt[b], 1);
        s_last = (old == NKVH * NCHUNK - 1);
    }
    __syncthreads();
    if (!s_last) return;
    __threadfence();

    {   // phase 1: combine chunk partials -> ctx[b][t] (in shared)
        int g = t >> 6, d = t & 63;
        int head = b * NQH + g;
        float M = -1e30f;
#pragma unroll
        for (int c = 0; c < NCHUNK; c++) M = fmaxf(M, g_pm[head * NCHUNK + c]);
        float L = 0.f, A = 0.f;
#pragma unroll
        for (int c = 0; c < NCHUNK; c++) {
            float e = __expf(g_pm[head * NCHUNK + c] - M);
            L += g_pl[head * NCHUNK + c] * e;
            A += g_pa[(size_t)(head * NCHUNK + c) * HD + d] * e;
        }
        sc[t] = A / L;
    }
    __syncthreads();

    {   // phase 2: output projection, thread-per-output (64 float4 loads)
        const float4* w4 = (const float4*)(out_w + (size_t)t * HIDDEN);
        float s = 0.f;
#pragma unroll
        for (int j = 0; j < HIDDEN / 4; j++) {
            float4 w = w4[j];
            s += w.x * sc[4 * j] + w.y * sc[4 * j + 1]
               + w.z * sc[4 * j + 2] + w.w * sc[4 * j + 3];
        }
        out[b * HIDDEN + t] = s;
    }

    // reset flags for the next graph replay (we are the last user of batch b)
    if (t == 0) { g_cnt[b] = 0; g_ready[b] = 0; }
}

// ---------------- launch ----------------------------------------------------
extern "C" void kernel_launch(void* const* d_in, const int* in_sizes, int n_in,
                              void* d_out, int out_size)
{
    const float* x     = (const float*)d_in[0];
    const float* kv    = (const float*)d_in[1];
    const int*   ctx   = (const int*)d_in[2];
    const float* rope  = (const float*)d_in[3];
    const float* qkv_w = (const float*)d_in[4];
    const float* qkv_b = (const float*)d_in[5];
    const float* out_w = (const float*)d_in[6];
    float* out = (float*)d_out;

    mega_kernel<<<NQKV_CTA + NWORK, 256>>>(x, kv, ctx, rope, qkv_w, qkv_b, out_w, out);
}

// round 5
// speedup vs baseline: 1.0333x; 1.0333x over previous
#include <cuda_runtime.h>

#define NB 32
#define HIDDEN 256
#define NQH 4
#define NKVH 2
#define HD 64
#define QKV_DIM 512
#define MAXS 8192
#define CHUNK 1024
#define NCHUNK (MAXS / CHUNK)          // 8
#define NHEAD (NB * NQH)               // 128
#define NWORK (NB * NKVH * NCHUNK)     // 512 worker CTAs

// ---------------- scratch (device globals) ----------------------------------
__device__ float g_q[NB * HIDDEN];
__device__ float g_k[NB * NKVH * HD];
__device__ float g_v[NB * NKVH * HD];
__device__ float g_pm[NHEAD * NCHUNK];
__device__ float g_pl[NHEAD * NCHUNK];
__device__ float g_pa[NHEAD * NCHUNK * HD];
__device__ int   g_cnt[NB];            // zero-init; reset by finisher

// ---------------- kernel 1: weight-stationary qkv projection + rope ---------
// grid 16 = (hid 0..7) x (batch-half 0..1). 256 threads = 64 d x 4 batch-groups.
// x for 16 batches lives in smem (broadcast reads); w streamed once per 4 thr.
__global__ void __launch_bounds__(256) qkv_rope_kernel(
    const float* __restrict__ x, const int* __restrict__ ctx_len,
    const float* __restrict__ rope, const float* __restrict__ qkv_w,
    const float* __restrict__ qkv_b)
{
    int hid = blockIdx.x >> 1;          // which 64-wide output head slice
    int bh  = blockIdx.x & 1;           // batch half: batches [bh*16, bh*16+16)
    int t = threadIdx.x;
    __shared__ float sx[16][HIDDEN];    // 16 KB
    __shared__ float sv[HD][17];        // results, padded (bank-conflict-free)

    // load x for 16 batches: 4096 floats = 1024 float4
    {
        const float4* x4 = (const float4*)(x + (size_t)bh * 16 * HIDDEN);
        float4* s4 = (float4*)&sx[0][0];
#pragma unroll
        for (int i = 0; i < 4; i++) s4[t + 256 * i] = x4[t + 256 * i];
    }
    __syncthreads();

    int d = t & 63, bg = t >> 6;        // bg in 0..3 -> batches bg*4..bg*4+3
    int e = hid * HD + d;
    float acc0 = 0.f, acc1 = 0.f, acc2 = 0.f, acc3 = 0.f;
    const float4* w4 = (const float4*)(qkv_w + (size_t)e * HIDDEN);

#pragma unroll 2
    for (int kt = 0; kt < 8; kt++) {    // 32 floats per tile
        float4 w[8];
#pragma unroll
        for (int j = 0; j < 8; j++) w[j] = w4[kt * 8 + j];
#pragma unroll
        for (int bi = 0; bi < 4; bi++) {
            const float4* xb = (const float4*)&sx[bg * 4 + bi][kt * 32];
            float s = 0.f;
#pragma unroll
            for (int j = 0; j < 8; j++) {
                float4 xv = xb[j];
                s += w[j].x * xv.x + w[j].y * xv.y + w[j].z * xv.z + w[j].w * xv.w;
            }
            if (bi == 0) acc0 += s; else if (bi == 1) acc1 += s;
            else if (bi == 2) acc2 += s; else acc3 += s;
        }
    }
    float bias = qkv_b[e];
    // stage into smem for rope pair exchange: sv[d][bl]
    // NOTE: each thread owns 4 batch-columns bg*4..bg*4+3 of row d
    {
        float a[4] = {acc0 + bias, acc1 + bias, acc2 + bias, acc3 + bias};
#pragma unroll
        for (int bi = 0; bi < 4; bi++) sv[d][bg * 4 + bi] = a[bi];
    }
    __syncthreads();

    // rope + scatter: each thread handles row d for its 4 batches
#pragma unroll
    for (int bi = 0; bi < 4; bi++) {
        int bl = bg * 4 + bi;
        int b = bh * 16 + bl;
        float v1 = sv[d][bl];
        float vp = sv[d ^ 32][bl];
        float val;
        if (hid < NQH + NKVH) {         // q or k: rope
            int pos = ctx_len[b];
            const float* cs = rope + (size_t)pos * HD;
            if (d < 32) val = v1 * cs[d] - vp * cs[d + 32];
            else        val = vp * cs[d] + v1 * cs[d - 32];
        } else {
            val = v1;
        }
        if (hid < NQH)             g_q[b * HIDDEN + hid * HD + d] = val;
        else if (hid < NQH + NKVH) g_k[(b * NKVH + (hid - NQH)) * HD + d] = val;
        else                       g_v[(b * NKVH + (hid - NQH - NKVH)) * HD + d] = val;
    }
}

// ---------------- kernel 2: fused cache copy + flash-decode + finisher ------
// 512 CTAs x 256 threads, single wave at 4 CTAs/SM.
__global__ void __launch_bounds__(256, 4) fused_attn_copy(
    const float* __restrict__ kv, const int* __restrict__ ctx_len,
    const float* __restrict__ out_w, float* __restrict__ out)
{
    int blk   = blockIdx.x;
    int chunk = blk & (NCHUNK - 1);
    int h     = (blk >> 3) & (NKVH - 1);
    int b     = blk >> 4;
    int t     = threadIdx.x;
    int warp  = t >> 5, lane = t & 31;
    int half  = lane >> 4, li = lane & 15;
    int pos   = ctx_len[b];

    size_t kb = (((size_t)b * 2 + 0) * NKVH + h) * (size_t)(MAXS * HD);
    size_t vb = kb + (size_t)NKVH * MAXS * HD;
    const float4* kp4 = (const float4*)(kv + kb);
    const float4* vp4 = (const float4*)(kv + vb);
    float4* okp4 = (float4*)(out + NB * HIDDEN + kb);
    float4* ovp4 = (float4*)(out + NB * HIDDEN + vb);

    int hq = h * 2;
    int d4 = li * 4;
    float4 q0 = *(const float4*)&g_q[((size_t)b * NQH + hq)     * HD + d4];
    float4 q1 = *(const float4*)&g_q[((size_t)b * NQH + hq + 1) * HD + d4];
    float4 kn = *(const float4*)&g_k[((size_t)b * NKVH + h) * HD + d4];
    float4 vn = *(const float4*)&g_v[((size_t)b * NKVH + h) * HD + d4];

    float m0 = -1e30f, l0 = 0.f, m1 = -1e30f, l1 = 0.f;
    float4 a0 = make_float4(0.f, 0.f, 0.f, 0.f);
    float4 a1 = make_float4(0.f, 0.f, 0.f, 0.f);
    const float scale = 0.125f;   // 64^-0.5

    int row0 = chunk * CHUNK + warp * (CHUNK / 8);
#pragma unroll 8
    for (int i = 0; i < CHUNK / 16; i++) {          // 2 rows per iter
        int m = row0 + 2 * i + half;                // per-half row
        size_t o4 = (size_t)m * (HD / 4) + li;
        float4 kd, vd;
        if (m == pos) { kd = kn; vd = vn; }
        else          { kd = __ldcs(kp4 + o4); vd = __ldcs(vp4 + o4); }
        __stcs(okp4 + o4, kd);
        __stcs(ovp4 + o4, vd);

        if (row0 + 2 * i <= pos) {                  // warp-uniform guard
            float p0 = kd.x * q0.x + kd.y * q0.y + kd.z * q0.z + kd.w * q0.w;
            float p1 = kd.x * q1.x + kd.y * q1.y + kd.z * q1.z + kd.w * q1.w;
#pragma unroll
            for (int sft = 8; sft > 0; sft >>= 1) { // stays within 16-lane half
                p0 += __shfl_xor_sync(0xffffffffu, p0, sft);
                p1 += __shfl_xor_sync(0xffffffffu, p1, sft);
            }
            if (m <= pos) {                          // per-half, ALU only
                p0 *= scale; p1 *= scale;
                float nm0 = fmaxf(m0, p0), nm1 = fmaxf(m1, p1);
                float f0 = __expf(m0 - nm0), w0 = __expf(p0 - nm0);
                float f1 = __expf(m1 - nm1), w1 = __expf(p1 - nm1);
                l0 = l0 * f0 + w0;  l1 = l1 * f1 + w1;
                a0.x = a0.x * f0 + w0 * vd.x;  a0.y = a0.y * f0 + w0 * vd.y;
                a0.z = a0.z * f0 + w0 * vd.z;  a0.w = a0.w * f0 + w0 * vd.w;
                a1.x = a1.x * f1 + w1 * vd.x;  a1.y = a1.y * f1 + w1 * vd.y;
                a1.z = a1.z * f1 + w1 * vd.z;  a1.w = a1.w * f1 + w1 * vd.w;
                m0 = nm0; m1 = nm1;
            }
        }
    }

    // merge the two half-warp streams (shfl_xor 16)
    {
        float mo = __shfl_xor_sync(0xffffffffu, m0, 16);
        float lo = __shfl_xor_sync(0xffffffffu, l0, 16);
        float4 ao;
        ao.x = __shfl_xor_sync(0xffffffffu, a0.x, 16);
        ao.y = __shfl_xor_sync(0xffffffffu, a0.y, 16);
        ao.z = __shfl_xor_sync(0xffffffffu, a0.z, 16);
        ao.w = __shfl_xor_sync(0xffffffffu, a0.w, 16);
        float M = fmaxf(m0, mo);
        float e0 = __expf(m0 - M), e1 = __expf(mo - M);
        l0 = l0 * e0 + lo * e1;
        a0.x = a0.x * e0 + ao.x * e1;  a0.y = a0.y * e0 + ao.y * e1;
        a0.z = a0.z * e0 + ao.z * e1;  a0.w = a0.w * e0 + ao.w * e1;
        m0 = M;
    }
    {
        float mo = __shfl_xor_sync(0xffffffffu, m1, 16);
        float lo = __shfl_xor_sync(0xffffffffu, l1, 16);
        float4 ao;
        ao.x = __shfl_xor_sync(0xffffffffu, a1.x, 16);
        ao.y = __shfl_xor_sync(0xffffffffu, a1.y, 16);
        ao.z = __shfl_xor_sync(0xffffffffu, a1.z, 16);
        ao.w = __shfl_xor_sync(0xffffffffu, a1.w, 16);
        float M = fmaxf(m1, mo);
        float e0 = __expf(m1 - M), e1 = __expf(mo - M);
        l1 = l1 * e0 + lo * e1;
        a1.x = a1.x * e0 + ao.x * e1;  a1.y = a1.y * e0 + ao.y * e1;
        a1.z = a1.z * e0 + ao.z * e1;  a1.w = a1.w * e0 + ao.w * e1;
        m1 = M;
    }

    // cross-warp combine -> per-CTA partial
    __shared__ float sm[2][8], sl[2][8], sa[2][8][HD];
    __shared__ float sc[HIDDEN];
    __shared__ int s_last;
    if (lane == 0) { sm[0][warp] = m0; sl[0][warp] = l0; sm[1][warp] = m1; sl[1][warp] = l1; }
    if (half == 0) {
        *(float4*)&sa[0][warp][d4] = a0;
        *(float4*)&sa[1][warp][d4] = a1;
    }
    __syncthreads();

    if (t < 128) {
        int g = t >> 6, d = t & 63;
        float M = -1e30f;
#pragma unroll
        for (int w = 0; w < 8; w++) M = fmaxf(M, sm[g][w]);
        float L = 0.f, A = 0.f;
#pragma unroll
        for (int w = 0; w < 8; w++) {
            float e = __expf(sm[g][w] - M);
            L += sl[g][w] * e;
            A += sa[g][w][d] * e;
        }
        int head = (b * NKVH + h) * 2 + g;
        int pi = head * NCHUNK + chunk;
        if (d == 0) { g_pm[pi] = M; g_pl[pi] = L; }
        g_pa[(size_t)pi * HD + d] = A;
    }

    // ---- finisher: last CTA of batch b combines + projects ----
    __threadfence();
    __syncthreads();
    if (t == 0) {
        int old = atomicAdd(&g_cnt[b], 1);
        s_last = (old == NKVH * NCHUNK - 1);
    }
    __syncthreads();
    if (!s_last) return;
    __threadfence();

    {   // combine chunk partials -> ctx[b][t] in shared
        int g = t >> 6, d = t & 63;
        int head = b * NQH + g;
        float M = -1e30f;
#pragma unroll
        for (int c = 0; c < NCHUNK; c++) M = fmaxf(M, g_pm[head * NCHUNK + c]);
        float L = 0.f, A = 0.f;
#pragma unroll
        for (int c = 0; c < NCHUNK; c++) {
            float e = __expf(g_pm[head * NCHUNK + c] - M);
            L += g_pl[head * NCHUNK + c] * e;
            A += g_pa[(size_t)(head * NCHUNK + c) * HD + d] * e;
        }
        sc[t] = A / L;
    }
    __syncthreads();

    {   // output projection: thread-per-output, 64 float4 loads
        const float4* w4 = (const float4*)(out_w + (size_t)t * HIDDEN);
        float s = 0.f;
#pragma unroll
        for (int j = 0; j < HIDDEN / 4; j++) {
            float4 w = w4[j];
            s += w.x * sc[4 * j] + w.y * sc[4 * j + 1]
               + w.z * sc[4 * j + 2] + w.w * sc[4 * j + 3];
        }
        out[b * HIDDEN + t] = s;
    }

    if (t == 0) g_cnt[b] = 0;   // reset for next graph replay
}

// ---------------- launch ----------------------------------------------------
extern "C" void kernel_launch(void* const* d_in, const int* in_sizes, int n_in,
                              void* d_out, int out_size)
{
    const float* x     = (const float*)d_in[0];
    const float* kv    = (const float*)d_in[1];
    const int*   ctx   = (const int*)d_in[2];
    const float* rope  = (const float*)d_in[3];
    const float* qkv_w = (const float*)d_in[4];
    const float* qkv_b = (const float*)d_in[5];
    const float* out_w = (const float*)d_in[6];
    float* out = (float*)d_out;

    qkv_rope_kernel<<<16, 256>>>(x, ctx, rope, qkv_w, qkv_b);
    fused_attn_copy<<<NWORK, 256>>>(kv, ctx, out_w, out);
}

// round 6
// speedup vs baseline: 1.1951x; 1.1567x over previous
#include <cuda_runtime.h>

#define NB 32
#define HIDDEN 256
#define NQH 4
#define NKVH 2
#define HD 64
#define QKV_DIM 512
#define MAXS 8192
#define CHUNK 512
#define NCHUNK (MAXS / CHUNK)          // 16
#define NHEAD (NB * NQH)               // 128

// ---------------- scratch (device globals) ----------------------------------
__device__ float g_q[NB * HIDDEN];
__device__ float g_k[NB * NKVH * HD];
__device__ float g_v[NB * NKVH * HD];
__device__ float g_pm[NHEAD * NCHUNK];
__device__ float g_pl[NHEAD * NCHUNK];
__device__ float g_pa[NHEAD * NCHUNK * HD];

// ---------------- kernel 1: weight-stationary qkv projection + rope ---------
// grid 16 = (hid 0..7) x (batch-half 0..1). 256 threads = 64 d x 4 batch-groups.
__global__ void __launch_bounds__(256) qkv_rope_kernel(
    const float* __restrict__ x, const int* __restrict__ ctx_len,
    const float* __restrict__ rope, const float* __restrict__ qkv_w,
    const float* __restrict__ qkv_b)
{
    int hid = blockIdx.x >> 1;          // which 64-wide output head slice
    int bh  = blockIdx.x & 1;           // batches [bh*16, bh*16+16)
    int t = threadIdx.x;
    __shared__ float sx[16][HIDDEN];
    __shared__ float sv[HD][17];

    {
        const float4* x4 = (const float4*)(x + (size_t)bh * 16 * HIDDEN);
        float4* s4 = (float4*)&sx[0][0];
#pragma unroll
        for (int i = 0; i < 4; i++) s4[t + 256 * i] = x4[t + 256 * i];
    }
    __syncthreads();

    int d = t & 63, bg = t >> 6;        // bg -> batches bg*4..bg*4+3
    int e = hid * HD + d;
    float acc0 = 0.f, acc1 = 0.f, acc2 = 0.f, acc3 = 0.f;
    const float4* w4 = (const float4*)(qkv_w + (size_t)e * HIDDEN);

#pragma unroll 2
    for (int kt = 0; kt < 8; kt++) {
        float4 w[8];
#pragma unroll
        for (int j = 0; j < 8; j++) w[j] = w4[kt * 8 + j];
#pragma unroll
        for (int bi = 0; bi < 4; bi++) {
            const float4* xb = (const float4*)&sx[bg * 4 + bi][kt * 32];
            float s = 0.f;
#pragma unroll
            for (int j = 0; j < 8; j++) {
                float4 xv = xb[j];
                s += w[j].x * xv.x + w[j].y * xv.y + w[j].z * xv.z + w[j].w * xv.w;
            }
            if (bi == 0) acc0 += s; else if (bi == 1) acc1 += s;
            else if (bi == 2) acc2 += s; else acc3 += s;
        }
    }
    float bias = qkv_b[e];
    {
        float a[4] = {acc0 + bias, acc1 + bias, acc2 + bias, acc3 + bias};
#pragma unroll
        for (int bi = 0; bi < 4; bi++) sv[d][bg * 4 + bi] = a[bi];
    }
    __syncthreads();

#pragma unroll
    for (int bi = 0; bi < 4; bi++) {
        int bl = bg * 4 + bi;
        int b = bh * 16 + bl;
        float v1 = sv[d][bl];
        float vp = sv[d ^ 32][bl];
        float val;
        if (hid < NQH + NKVH) {         // q or k: rope
            int pos = ctx_len[b];
            const float* cs = rope + (size_t)pos * HD;
            if (d < 32) val = v1 * cs[d] - vp * cs[d + 32];
            else        val = vp * cs[d] + v1 * cs[d - 32];
        } else {
            val = v1;
        }
        if (hid < NQH)             g_q[b * HIDDEN + hid * HD + d] = val;
        else if (hid < NQH + NKVH) g_k[(b * NKVH + (hid - NQH)) * HD + d] = val;
        else                       g_v[(b * NKVH + (hid - NQH - NKVH)) * HD + d] = val;
    }
}

// ---------------- kernel 2: fused KV-cache copy + flash-decode partials -----
// 1024 CTAs x 256 threads (R3-proven config).
__global__ void __launch_bounds__(256) fused_attn_copy(
    const float* __restrict__ kv, const int* __restrict__ ctx_len,
    float* __restrict__ out)
{
    int blk   = blockIdx.x;
    int chunk = blk & (NCHUNK - 1);
    int h     = (blk >> 4) & (NKVH - 1);
    int b     = blk >> 5;
    int warp  = threadIdx.x >> 5, lane = threadIdx.x & 31;
    int half  = lane >> 4, li = lane & 15;
    int pos   = ctx_len[b];

    size_t kb = (((size_t)b * 2 + 0) * NKVH + h) * (size_t)(MAXS * HD);
    size_t vb = kb + (size_t)NKVH * MAXS * HD;
    const float4* kp4 = (const float4*)(kv + kb);
    const float4* vp4 = (const float4*)(kv + vb);
    float4* okp4 = (float4*)(out + NB * HIDDEN + kb);
    float4* ovp4 = (float4*)(out + NB * HIDDEN + vb);

    int hq = h * 2;
    int d4 = li * 4;
    float4 q0 = *(const float4*)&g_q[((size_t)b * NQH + hq)     * HD + d4];
    float4 q1 = *(const float4*)&g_q[((size_t)b * NQH + hq + 1) * HD + d4];
    float4 kn = *(const float4*)&g_k[((size_t)b * NKVH + h) * HD + d4];
    float4 vn = *(const float4*)&g_v[((size_t)b * NKVH + h) * HD + d4];

    float m0 = -1e30f, l0 = 0.f, m1 = -1e30f, l1 = 0.f;
    float4 a0 = make_float4(0.f, 0.f, 0.f, 0.f);
    float4 a1 = make_float4(0.f, 0.f, 0.f, 0.f);
    const float scale = 0.125f;   // 64^-0.5

    int row0 = chunk * CHUNK + warp * (CHUNK / 8);
#pragma unroll 8
    for (int i = 0; i < CHUNK / 16; i++) {          // 2 rows per iter
        int m = row0 + 2 * i + half;                // per-half row
        size_t o4 = (size_t)m * (HD / 4) + li;
        float4 kd, vd;
        if (m == pos) { kd = kn; vd = vn; }
        else          { kd = __ldcs(kp4 + o4); vd = __ldcs(vp4 + o4); }
        __stcs(okp4 + o4, kd);
        __stcs(ovp4 + o4, vd);

        if (row0 + 2 * i <= pos) {                  // warp-uniform guard
            float p0 = kd.x * q0.x + kd.y * q0.y + kd.z * q0.z + kd.w * q0.w;
            float p1 = kd.x * q1.x + kd.y * q1.y + kd.z * q1.z + kd.w * q1.w;
#pragma unroll
            for (int sft = 8; sft > 0; sft >>= 1) { // stays within 16-lane half
                p0 += __shfl_xor_sync(0xffffffffu, p0, sft);
                p1 += __shfl_xor_sync(0xffffffffu, p1, sft);
            }
            if (m <= pos) {                          // per-half, ALU only
                p0 *= scale; p1 *= scale;
                float nm0 = fmaxf(m0, p0), nm1 = fmaxf(m1, p1);
                float f0 = __expf(m0 - nm0), w0 = __expf(p0 - nm0);
                float f1 = __expf(m1 - nm1), w1 = __expf(p1 - nm1);
                l0 = l0 * f0 + w0;  l1 = l1 * f1 + w1;
                a0.x = a0.x * f0 + w0 * vd.x;  a0.y = a0.y * f0 + w0 * vd.y;
                a0.z = a0.z * f0 + w0 * vd.z;  a0.w = a0.w * f0 + w0 * vd.w;
                a1.x = a1.x * f1 + w1 * vd.x;  a1.y = a1.y * f1 + w1 * vd.y;
                a1.z = a1.z * f1 + w1 * vd.z;  a1.w = a1.w * f1 + w1 * vd.w;
                m0 = nm0; m1 = nm1;
            }
        }
    }

    // merge the two half-warp softmax streams per head (shfl_xor 16)
    {
        float mo = __shfl_xor_sync(0xffffffffu, m0, 16);
        float lo = __shfl_xor_sync(0xffffffffu, l0, 16);
        float4 ao;
        ao.x = __shfl_xor_sync(0xffffffffu, a0.x, 16);
        ao.y = __shfl_xor_sync(0xffffffffu, a0.y, 16);
        ao.z = __shfl_xor_sync(0xffffffffu, a0.z, 16);
        ao.w = __shfl_xor_sync(0xffffffffu, a0.w, 16);
        float M = fmaxf(m0, mo);
        float e0 = __expf(m0 - M), e1 = __expf(mo - M);
        l0 = l0 * e0 + lo * e1;
        a0.x = a0.x * e0 + ao.x * e1;  a0.y = a0.y * e0 + ao.y * e1;
        a0.z = a0.z * e0 + ao.z * e1;  a0.w = a0.w * e0 + ao.w * e1;
        m0 = M;
    }
    {
        float mo = __shfl_xor_sync(0xffffffffu, m1, 16);
        float lo = __shfl_xor_sync(0xffffffffu, l1, 16);
        float4 ao;
        ao.x = __shfl_xor_sync(0xffffffffu, a1.x, 16);
        ao.y = __shfl_xor_sync(0xffffffffu, a1.y, 16);
        ao.z = __shfl_xor_sync(0xffffffffu, a1.z, 16);
        ao.w = __shfl_xor_sync(0xffffffffu, a1.w, 16);
        float M = fmaxf(m1, mo);
        float e0 = __expf(m1 - M), e1 = __expf(mo - M);
        l1 = l1 * e0 + lo * e1;
        a1.x = a1.x * e0 + ao.x * e1;  a1.y = a1.y * e0 + ao.y * e1;
        a1.z = a1.z * e0 + ao.z * e1;  a1.w = a1.w * e0 + ao.w * e1;
        m1 = M;
    }

    // cross-warp combine
    __shared__ float sm[2][8], sl[2][8], sa[2][8][HD];
    if (lane == 0) { sm[0][warp] = m0; sl[0][warp] = l0; sm[1][warp] = m1; sl[1][warp] = l1; }
    if (half == 0) {
        *(float4*)&sa[0][warp][d4] = a0;
        *(float4*)&sa[1][warp][d4] = a1;
    }
    __syncthreads();

    int t = threadIdx.x;
    if (t < 128) {
        int g = t >> 6, d = t & 63;
        float M = -1e30f;
#pragma unroll
        for (int w = 0; w < 8; w++) M = fmaxf(M, sm[g][w]);
        float L = 0.f, A = 0.f;
#pragma unroll
        for (int w = 0; w < 8; w++) {
            float e = __expf(sm[g][w] - M);
            L += sl[g][w] * e;
            A += sa[g][w][d] * e;
        }
        int head = (b * NKVH + h) * 2 + g;
        int pi = head * NCHUNK + chunk;
        if (d == 0) { g_pm[pi] = M; g_pl[pi] = L; }
        g_pa[(size_t)pi * HD + d] = A;
    }
}

// ---------------- kernel 3: combine + output projection ---------------------
// grid (8, NB), 256 threads.
__global__ void __launch_bounds__(256) outproj_kernel(
    const float* __restrict__ out_w, float* __restrict__ out)
{
    int b = blockIdx.y, t = threadIdx.x;
    __shared__ float sc[HIDDEN];

    {   // phase 1: combine chunk partials -> ctx[b][t]
        int g = t >> 6, d = t & 63;
        int head = b * NQH + g;
        float M = -1e30f;
#pragma unroll
        for (int c = 0; c < NCHUNK; c++) M = fmaxf(M, g_pm[head * NCHUNK + c]);
        float L = 0.f, A = 0.f;
#pragma unroll
        for (int c = 0; c < NCHUNK; c++) {
            float e = __expf(g_pm[head * NCHUNK + c] - M);
            L += g_pl[head * NCHUNK + c] * e;
            A += g_pa[(size_t)(head * NCHUNK + c) * HD + d] * e;
        }
        sc[t] = A / L;
    }
    __syncthreads();

    // phase 2: projection, 8 threads per output element
    int e = blockIdx.x * 32 + (t >> 3);
    int part = t & 7;
    const float4* w4 = (const float4*)(out_w + (size_t)e * HIDDEN + part * 32);
    const float*  c  = sc + part * 32;
    float s = 0.f;
#pragma unroll
    for (int j = 0; j < 8; j++) {
        float4 w = w4[j];
        s += w.x * c[4 * j] + w.y * c[4 * j + 1] + w.z * c[4 * j + 2] + w.w * c[4 * j + 3];
    }
    s += __shfl_xor_sync(0xffffffffu, s, 1);
    s += __shfl_xor_sync(0xffffffffu, s, 2);
    s += __shfl_xor_sync(0xffffffffu, s, 4);
    if (part == 0) out[b * HIDDEN + e] = s;
}

// ---------------- launch ----------------------------------------------------
extern "C" void kernel_launch(void* const* d_in, const int* in_sizes, int n_in,
                              void* d_out, int out_size)
{
    const float* x     = (const float*)d_in[0];
    const float* kv    = (const float*)d_in[1];
    const int*   ctx   = (const int*)d_in[2];
    const float* rope  = (const float*)d_in[3];
    const float* qkv_w = (const float*)d_in[4];
    const float* qkv_b = (const float*)d_in[5];
    const float* out_w = (const float*)d_in[6];
    float* out = (float*)d_out;

    qkv_rope_kernel<<<16, 256>>>(x, ctx, rope, qkv_w, qkv_b);
    fused_attn_copy<<<NB * NKVH * NCHUNK, 256>>>(kv, ctx, out);
    outproj_kernel<<<dim3(8, NB), 256>>>(out_w, out);
}

// round 7
// speedup vs baseline: 1.3202x; 1.1047x over previous
#include <cuda_runtime.h>

#define NB 32
#define HIDDEN 256
#define NQH 4
#define NKVH 2
#define HD 64
#define QKV_DIM 512
#define MAXS 8192
#define CHUNK 512
#define NCHUNK (MAXS / CHUNK)          // 16
#define NHEAD (NB * NQH)               // 128

// ---------------- scratch (device globals) ----------------------------------
__device__ float g_q[NB * HIDDEN];
__device__ float g_k[NB * NKVH * HD];
__device__ float g_v[NB * NKVH * HD];
__device__ float g_pm[NHEAD * NCHUNK];
__device__ float g_pl[NHEAD * NCHUNK];
__device__ float g_pa[NHEAD * NCHUNK * HD];

__device__ __forceinline__ float dot4(float4 a, float4 b) {
    return a.x * b.x + a.y * b.y + a.z * b.z + a.w * b.w;
}

// ---------------- kernel 1: qkv projection + rope, warp-per-rope-pair -------
// 8192 warps: warp W -> batch b = W&31, pair-dim d = (W>>5)&31, head-slice
// hid = W>>10. Computes outputs e=hid*64+d and e+32 (the rope pair) for b.
// Each lane: 6 independent float4 loads -> chain depth 1.
__global__ void __launch_bounds__(256) qkv_rope_kernel(
    const float* __restrict__ x, const int* __restrict__ ctx_len,
    const float* __restrict__ rope, const float* __restrict__ qkv_w,
    const float* __restrict__ qkv_b)
{
    int W    = blockIdx.x * 8 + (threadIdx.x >> 5);
    int lane = threadIdx.x & 31;
    int b    = W & 31;
    int d    = (W >> 5) & 31;
    int hid  = W >> 10;                   // 0..7
    int elo  = hid * HD + d;              // low output row
    int ehi  = elo + 32;                  // rope partner row

    const float4* wlo = (const float4*)(qkv_w + (size_t)elo * HIDDEN) + lane * 2;
    const float4* whi = (const float4*)(qkv_w + (size_t)ehi * HIDDEN) + lane * 2;
    const float4* xb  = (const float4*)(x + (size_t)b * HIDDEN) + lane * 2;

    float4 wl0 = wlo[0], wl1 = wlo[1];
    float4 wh0 = whi[0], wh1 = whi[1];
    float4 x0  = xb[0],  x1  = xb[1];

    float slo = dot4(wl0, x0) + dot4(wl1, x1);
    float shi = dot4(wh0, x0) + dot4(wh1, x1);
#pragma unroll
    for (int s = 16; s > 0; s >>= 1) {
        slo += __shfl_xor_sync(0xffffffffu, slo, s);
        shi += __shfl_xor_sync(0xffffffffu, shi, s);
    }

    if (lane == 0) {
        slo += qkv_b[elo];
        shi += qkv_b[ehi];
        float vlo, vhi;
        if (hid < NQH + NKVH) {           // q or k: rope
            int pos = ctx_len[b];
            float c = rope[(size_t)pos * HD + d];
            float s = rope[(size_t)pos * HD + 32 + d];
            vlo = slo * c - shi * s;
            vhi = slo * s + shi * c;
        } else {                          // v
            vlo = slo; vhi = shi;
        }
        if (hid < NQH) {
            g_q[b * HIDDEN + hid * HD + d]      = vlo;
            g_q[b * HIDDEN + hid * HD + d + 32] = vhi;
        } else if (hid < NQH + NKVH) {
            int hk = hid - NQH;
            g_k[(b * NKVH + hk) * HD + d]      = vlo;
            g_k[(b * NKVH + hk) * HD + d + 32] = vhi;
        } else {
            int hv = hid - NQH - NKVH;
            g_v[(b * NKVH + hv) * HD + d]      = vlo;
            g_v[(b * NKVH + hv) * HD + d + 32] = vhi;
        }
    }
}

// ---------------- kernel 2: fused KV-cache copy + flash-decode partials -----
// 1024 CTAs x 256 threads (R3-proven config — unchanged).
__global__ void __launch_bounds__(256) fused_attn_copy(
    const float* __restrict__ kv, const int* __restrict__ ctx_len,
    float* __restrict__ out)
{
    int blk   = blockIdx.x;
    int chunk = blk & (NCHUNK - 1);
    int h     = (blk >> 4) & (NKVH - 1);
    int b     = blk >> 5;
    int warp  = threadIdx.x >> 5, lane = threadIdx.x & 31;
    int half  = lane >> 4, li = lane & 15;
    int pos   = ctx_len[b];

    size_t kb = (((size_t)b * 2 + 0) * NKVH + h) * (size_t)(MAXS * HD);
    size_t vb = kb + (size_t)NKVH * MAXS * HD;
    const float4* kp4 = (const float4*)(kv + kb);
    const float4* vp4 = (const float4*)(kv + vb);
    float4* okp4 = (float4*)(out + NB * HIDDEN + kb);
    float4* ovp4 = (float4*)(out + NB * HIDDEN + vb);

    int hq = h * 2;
    int d4 = li * 4;
    float4 q0 = *(const float4*)&g_q[((size_t)b * NQH + hq)     * HD + d4];
    float4 q1 = *(const float4*)&g_q[((size_t)b * NQH + hq + 1) * HD + d4];
    float4 kn = *(const float4*)&g_k[((size_t)b * NKVH + h) * HD + d4];
    float4 vn = *(const float4*)&g_v[((size_t)b * NKVH + h) * HD + d4];

    float m0 = -1e30f, l0 = 0.f, m1 = -1e30f, l1 = 0.f;
    float4 a0 = make_float4(0.f, 0.f, 0.f, 0.f);
    float4 a1 = make_float4(0.f, 0.f, 0.f, 0.f);
    const float scale = 0.125f;   // 64^-0.5

    int row0 = chunk * CHUNK + warp * (CHUNK / 8);
#pragma unroll 8
    for (int i = 0; i < CHUNK / 16; i++) {          // 2 rows per iter
        int m = row0 + 2 * i + half;                // per-half row
        size_t o4 = (size_t)m * (HD / 4) + li;
        float4 kd, vd;
        if (m == pos) { kd = kn; vd = vn; }
        else          { kd = __ldcs(kp4 + o4); vd = __ldcs(vp4 + o4); }
        __stcs(okp4 + o4, kd);
        __stcs(ovp4 + o4, vd);

        if (row0 + 2 * i <= pos) {                  // warp-uniform guard
            float p0 = kd.x * q0.x + kd.y * q0.y + kd.z * q0.z + kd.w * q0.w;
            float p1 = kd.x * q1.x + kd.y * q1.y + kd.z * q1.z + kd.w * q1.w;
#pragma unroll
            for (int sft = 8; sft > 0; sft >>= 1) { // stays within 16-lane half
                p0 += __shfl_xor_sync(0xffffffffu, p0, sft);
                p1 += __shfl_xor_sync(0xffffffffu, p1, sft);
            }
            if (m <= pos) {                          // per-half, ALU only
                p0 *= scale; p1 *= scale;
                float nm0 = fmaxf(m0, p0), nm1 = fmaxf(m1, p1);
                float f0 = __expf(m0 - nm0), w0 = __expf(p0 - nm0);
                float f1 = __expf(m1 - nm1), w1 = __expf(p1 - nm1);
                l0 = l0 * f0 + w0;  l1 = l1 * f1 + w1;
                a0.x = a0.x * f0 + w0 * vd.x;  a0.y = a0.y * f0 + w0 * vd.y;
                a0.z = a0.z * f0 + w0 * vd.z;  a0.w = a0.w * f0 + w0 * vd.w;
                a1.x = a1.x * f1 + w1 * vd.x;  a1.y = a1.y * f1 + w1 * vd.y;
                a1.z = a1.z * f1 + w1 * vd.z;  a1.w = a1.w * f1 + w1 * vd.w;
                m0 = nm0; m1 = nm1;
            }
        }
    }

    // merge the two half-warp softmax streams per head (shfl_xor 16)
    {
        float mo = __shfl_xor_sync(0xffffffffu, m0, 16);
        float lo = __shfl_xor_sync(0xffffffffu, l0, 16);
        float4 ao;
        ao.x = __shfl_xor_sync(0xffffffffu, a0.x, 16);
        ao.y = __shfl_xor_sync(0xffffffffu, a0.y, 16);
        ao.z = __shfl_xor_sync(0xffffffffu, a0.z, 16);
        ao.w = __shfl_xor_sync(0xffffffffu, a0.w, 16);
        float M = fmaxf(m0, mo);
        float e0 = __expf(m0 - M), e1 = __expf(mo - M);
        l0 = l0 * e0 + lo * e1;
        a0.x = a0.x * e0 + ao.x * e1;  a0.y = a0.y * e0 + ao.y * e1;
        a0.z = a0.z * e0 + ao.z * e1;  a0.w = a0.w * e0 + ao.w * e1;
        m0 = M;
    }
    {
        float mo = __shfl_xor_sync(0xffffffffu, m1, 16);
        float lo = __shfl_xor_sync(0xffffffffu, l1, 16);
        float4 ao;
        ao.x = __shfl_xor_sync(0xffffffffu, a1.x, 16);
        ao.y = __shfl_xor_sync(0xffffffffu, a1.y, 16);
        ao.z = __shfl_xor_sync(0xffffffffu, a1.z, 16);
        ao.w = __shfl_xor_sync(0xffffffffu, a1.w, 16);
        float M = fmaxf(m1, mo);
        float e0 = __expf(m1 - M), e1 = __expf(mo - M);
        l1 = l1 * e0 + lo * e1;
        a1.x = a1.x * e0 + ao.x * e1;  a1.y = a1.y * e0 + ao.y * e1;
        a1.z = a1.z * e0 + ao.z * e1;  a1.w = a1.w * e0 + ao.w * e1;
        m1 = M;
    }

    // cross-warp combine
    __shared__ float sm[2][8], sl[2][8], sa[2][8][HD];
    if (lane == 0) { sm[0][warp] = m0; sl[0][warp] = l0; sm[1][warp] = m1; sl[1][warp] = l1; }
    if (half == 0) {
        *(float4*)&sa[0][warp][d4] = a0;
        *(float4*)&sa[1][warp][d4] = a1;
    }
    __syncthreads();

    int t = threadIdx.x;
    if (t < 128) {
        int g = t >> 6, d = t & 63;
        float M = -1e30f;
#pragma unroll
        for (int w = 0; w < 8; w++) M = fmaxf(M, sm[g][w]);
        float L = 0.f, A = 0.f;
#pragma unroll
        for (int w = 0; w < 8; w++) {
            float e = __expf(sm[g][w] - M);
            L += sl[g][w] * e;
            A += sa[g][w][d] * e;
        }
        int head = (b * NKVH + h) * 2 + g;
        int pi = head * NCHUNK + chunk;
        if (d == 0) { g_pm[pi] = M; g_pl[pi] = L; }
        g_pa[(size_t)pi * HD + d] = A;
    }
}

// ---------------- kernel 3: combine + output projection, warp-per-output ----
// grid 1024: blk -> b = blk>>5, eblk = blk&31 (8 outputs). 256 threads.
__global__ void __launch_bounds__(256) outproj_kernel(
    const float* __restrict__ out_w, float* __restrict__ out)
{
    int blk = blockIdx.x;
    int b = blk >> 5, eblk = blk & 31;
    int t = threadIdx.x;
    __shared__ float sc[HIDDEN];

    {   // phase 1: combine chunk partials -> ctx[b][t] (loads pipeline: 16 indep)
        int g = t >> 6, d = t & 63;
        int head = b * NQH + g;
        float M = -1e30f;
#pragma unroll
        for (int c = 0; c < NCHUNK; c++) M = fmaxf(M, g_pm[head * NCHUNK + c]);
        float L = 0.f, A = 0.f;
#pragma unroll
        for (int c = 0; c < NCHUNK; c++) {
            float e = __expf(g_pm[head * NCHUNK + c] - M);
            L += g_pl[head * NCHUNK + c] * e;
            A += g_pa[(size_t)(head * NCHUNK + c) * HD + d] * e;
        }
        sc[t] = A / L;
    }
    __syncthreads();

    // phase 2: warp w computes output e = eblk*8 + w (chain depth 1: 2 loads)
    int w = t >> 5, lane = t & 31;
    int e = eblk * 8 + w;
    const float4* w4 = (const float4*)(out_w + (size_t)e * HIDDEN) + lane * 2;
    const float4* c4 = (const float4*)sc + lane * 2;
    float4 wa = w4[0], wb = w4[1];
    float s = dot4(wa, c4[0]) + dot4(wb, c4[1]);
#pragma unroll
    for (int sft = 16; sft > 0; sft >>= 1)
        s += __shfl_xor_sync(0xffffffffu, s, sft);
    if (lane == 0) out[b * HIDDEN + e] = s;
}

// ---------------- launch ----------------------------------------------------
extern "C" void kernel_launch(void* const* d_in, const int* in_sizes, int n_in,
                              void* d_out, int out_size)
{
    const float* x     = (const float*)d_in[0];
    const float* kv    = (const float*)d_in[1];
    const int*   ctx   = (const int*)d_in[2];
    const float* rope  = (const float*)d_in[3];
    const float* qkv_w = (const float*)d_in[4];
    const float* qkv_b = (const float*)d_in[5];
    const float* out_w = (const float*)d_in[6];
    float* out = (float*)d_out;

    qkv_rope_kernel<<<1024, 256>>>(x, ctx, rope, qkv_w, qkv_b);
    fused_attn_copy<<<NB * NKVH * NCHUNK, 256>>>(kv, ctx, out);
    outproj_kernel<<<1024, 256>>>(out_w, out);
}

// round 8
// speedup vs baseline: 1.3210x; 1.0006x over previous
#include <cuda_runtime.h>

#define NB 32
#define HIDDEN 256
#define NQH 4
#define NKVH 2
#define HD 64
#define QKV_DIM 512
#define MAXS 8192
#define CHUNK 512
#define NCHUNK (MAXS / CHUNK)          // 16
#define NHEAD (NB * NQH)               // 128

// ---------------- scratch (device globals) ----------------------------------
__device__ float g_q[NB * HIDDEN];
__device__ float g_k[NB * NKVH * HD];
__device__ float g_v[NB * NKVH * HD];
__device__ float g_pm[NHEAD * NCHUNK];
__device__ float g_pl[NHEAD * NCHUNK];
__device__ float g_pa[NHEAD * NCHUNK * HD];

__device__ __forceinline__ float dot4(float4 a, float4 b) {
    return a.x * b.x + a.y * b.y + a.z * b.z + a.w * b.w;
}

// ---------------- kernel 1: qkv projection + rope ---------------------------
// grid 256 x 256 thr = 2048 warps. Warp W -> bq = W&7 (batches bq*4..bq*4+3),
// d = (W>>3)&31, hid = W>>8. Weight rows loaded ONCE per warp, reused for 4
// batches -> 4MB L2 weight traffic instead of 16MB.
__global__ void __launch_bounds__(256) qkv_rope_kernel(
    const float* __restrict__ x, const int* __restrict__ ctx_len,
    const float* __restrict__ rope, const float* __restrict__ qkv_w,
    const float* __restrict__ qkv_b)
{
    int W    = blockIdx.x * 8 + (threadIdx.x >> 5);
    int lane = threadIdx.x & 31;
    int bq   = W & 7;                     // batch quad
    int d    = (W >> 3) & 31;
    int hid  = W >> 8;                    // 0..7
    int elo  = hid * HD + d;
    int ehi  = elo + 32;

    const float4* wlo = (const float4*)(qkv_w + (size_t)elo * HIDDEN) + lane * 2;
    const float4* whi = (const float4*)(qkv_w + (size_t)ehi * HIDDEN) + lane * 2;
    float4 wl0 = wlo[0], wl1 = wlo[1];
    float4 wh0 = whi[0], wh1 = whi[1];

    float slo[4], shi[4];
#pragma unroll
    for (int bi = 0; bi < 4; bi++) {
        int b = bq * 4 + bi;
        const float4* xb = (const float4*)(x + (size_t)b * HIDDEN) + lane * 2;
        float4 x0 = xb[0], x1 = xb[1];
        slo[bi] = dot4(wl0, x0) + dot4(wl1, x1);
        shi[bi] = dot4(wh0, x0) + dot4(wh1, x1);
    }
#pragma unroll
    for (int s = 16; s > 0; s >>= 1) {
#pragma unroll
        for (int bi = 0; bi < 4; bi++) {
            slo[bi] += __shfl_xor_sync(0xffffffffu, slo[bi], s);
            shi[bi] += __shfl_xor_sync(0xffffffffu, shi[bi], s);
        }
    }

    if (lane == 0) {
        float blo = qkv_b[elo], bhi = qkv_b[ehi];
#pragma unroll
        for (int bi = 0; bi < 4; bi++) {
            int b = bq * 4 + bi;
            float lo = slo[bi] + blo, hi = shi[bi] + bhi;
            float vlo, vhi;
            if (hid < NQH + NKVH) {       // q or k: rope
                int pos = ctx_len[b];
                float c = rope[(size_t)pos * HD + d];
                float s = rope[(size_t)pos * HD + 32 + d];
                vlo = lo * c - hi * s;
                vhi = lo * s + hi * c;
            } else {
                vlo = lo; vhi = hi;
            }
            if (hid < NQH) {
                g_q[b * HIDDEN + hid * HD + d]      = vlo;
                g_q[b * HIDDEN + hid * HD + d + 32] = vhi;
            } else if (hid < NQH + NKVH) {
                int hk = hid - NQH;
                g_k[(b * NKVH + hk) * HD + d]      = vlo;
                g_k[(b * NKVH + hk) * HD + d + 32] = vhi;
            } else {
                int hv = hid - NQH - NKVH;
                g_v[(b * NKVH + hv) * HD + d]      = vlo;
                g_v[(b * NKVH + hv) * HD + d + 32] = vhi;
            }
        }
    }
}

// ---------------- kernel 2: fused KV-cache copy + flash-decode partials -----
// 1024 CTAs x 256 threads (R3-proven config — unchanged).
__global__ void __launch_bounds__(256) fused_attn_copy(
    const float* __restrict__ kv, const int* __restrict__ ctx_len,
    float* __restrict__ out)
{
    int blk   = blockIdx.x;
    int chunk = blk & (NCHUNK - 1);
    int h     = (blk >> 4) & (NKVH - 1);
    int b     = blk >> 5;
    int warp  = threadIdx.x >> 5, lane = threadIdx.x & 31;
    int half  = lane >> 4, li = lane & 15;
    int pos   = ctx_len[b];

    size_t kb = (((size_t)b * 2 + 0) * NKVH + h) * (size_t)(MAXS * HD);
    size_t vb = kb + (size_t)NKVH * MAXS * HD;
    const float4* kp4 = (const float4*)(kv + kb);
    const float4* vp4 = (const float4*)(kv + vb);
    float4* okp4 = (float4*)(out + NB * HIDDEN + kb);
    float4* ovp4 = (float4*)(out + NB * HIDDEN + vb);

    int hq = h * 2;
    int d4 = li * 4;
    float4 q0 = *(const float4*)&g_q[((size_t)b * NQH + hq)     * HD + d4];
    float4 q1 = *(const float4*)&g_q[((size_t)b * NQH + hq + 1) * HD + d4];
    float4 kn = *(const float4*)&g_k[((size_t)b * NKVH + h) * HD + d4];
    float4 vn = *(const float4*)&g_v[((size_t)b * NKVH + h) * HD + d4];

    float m0 = -1e30f, l0 = 0.f, m1 = -1e30f, l1 = 0.f;
    float4 a0 = make_float4(0.f, 0.f, 0.f, 0.f);
    float4 a1 = make_float4(0.f, 0.f, 0.f, 0.f);
    const float scale = 0.125f;   // 64^-0.5

    int row0 = chunk * CHUNK + warp * (CHUNK / 8);
#pragma unroll 8
    for (int i = 0; i < CHUNK / 16; i++) {          // 2 rows per iter
        int m = row0 + 2 * i + half;                // per-half row
        size_t o4 = (size_t)m * (HD / 4) + li;
        float4 kd, vd;
        if (m == pos) { kd = kn; vd = vn; }
        else          { kd = __ldcs(kp4 + o4); vd = __ldcs(vp4 + o4); }
        __stcs(okp4 + o4, kd);
        __stcs(ovp4 + o4, vd);

        if (row0 + 2 * i <= pos) {                  // warp-uniform guard
            float p0 = kd.x * q0.x + kd.y * q0.y + kd.z * q0.z + kd.w * q0.w;
            float p1 = kd.x * q1.x + kd.y * q1.y + kd.z * q1.z + kd.w * q1.w;
#pragma unroll
            for (int sft = 8; sft > 0; sft >>= 1) { // stays within 16-lane half
                p0 += __shfl_xor_sync(0xffffffffu, p0, sft);
                p1 += __shfl_xor_sync(0xffffffffu, p1, sft);
            }
            if (m <= pos) {                          // per-half, ALU only
                p0 *= scale; p1 *= scale;
                float nm0 = fmaxf(m0, p0), nm1 = fmaxf(m1, p1);
                float f0 = __expf(m0 - nm0), w0 = __expf(p0 - nm0);
                float f1 = __expf(m1 - nm1), w1 = __expf(p1 - nm1);
                l0 = l0 * f0 + w0;  l1 = l1 * f1 + w1;
                a0.x = a0.x * f0 + w0 * vd.x;  a0.y = a0.y * f0 + w0 * vd.y;
                a0.z = a0.z * f0 + w0 * vd.z;  a0.w = a0.w * f0 + w0 * vd.w;
                a1.x = a1.x * f1 + w1 * vd.x;  a1.y = a1.y * f1 + w1 * vd.y;
                a1.z = a1.z * f1 + w1 * vd.z;  a1.w = a1.w * f1 + w1 * vd.w;
                m0 = nm0; m1 = nm1;
            }
        }
    }

    // merge the two half-warp softmax streams per head (shfl_xor 16)
    {
        float mo = __shfl_xor_sync(0xffffffffu, m0, 16);
        float lo = __shfl_xor_sync(0xffffffffu, l0, 16);
        float4 ao;
        ao.x = __shfl_xor_sync(0xffffffffu, a0.x, 16);
        ao.y = __shfl_xor_sync(0xffffffffu, a0.y, 16);
        ao.z = __shfl_xor_sync(0xffffffffu, a0.z, 16);
        ao.w = __shfl_xor_sync(0xffffffffu, a0.w, 16);
        float M = fmaxf(m0, mo);
        float e0 = __expf(m0 - M), e1 = __expf(mo - M);
        l0 = l0 * e0 + lo * e1;
        a0.x = a0.x * e0 + ao.x * e1;  a0.y = a0.y * e0 + ao.y * e1;
        a0.z = a0.z * e0 + ao.z * e1;  a0.w = a0.w * e0 + ao.w * e1;
        m0 = M;
    }
    {
        float mo = __shfl_xor_sync(0xffffffffu, m1, 16);
        float lo = __shfl_xor_sync(0xffffffffu, l1, 16);
        float4 ao;
        ao.x = __shfl_xor_sync(0xffffffffu, a1.x, 16);
        ao.y = __shfl_xor_sync(0xffffffffu, a1.y, 16);
        ao.z = __shfl_xor_sync(0xffffffffu, a1.z, 16);
        ao.w = __shfl_xor_sync(0xffffffffu, a1.w, 16);
        float M = fmaxf(m1, mo);
        float e0 = __expf(m1 - M), e1 = __expf(mo - M);
        l1 = l1 * e0 + lo * e1;
        a1.x = a1.x * e0 + ao.x * e1;  a1.y = a1.y * e0 + ao.y * e1;
        a1.z = a1.z * e0 + ao.z * e1;  a1.w = a1.w * e0 + ao.w * e1;
        m1 = M;
    }

    // cross-warp combine
    __shared__ float sm[2][8], sl[2][8], sa[2][8][HD];
    if (lane == 0) { sm[0][warp] = m0; sl[0][warp] = l0; sm[1][warp] = m1; sl[1][warp] = l1; }
    if (half == 0) {
        *(float4*)&sa[0][warp][d4] = a0;
        *(float4*)&sa[1][warp][d4] = a1;
    }
    __syncthreads();

    int t = threadIdx.x;
    if (t < 128) {
        int g = t >> 6, d = t & 63;
        float M = -1e30f;
#pragma unroll
        for (int w = 0; w < 8; w++) M = fmaxf(M, sm[g][w]);
        float L = 0.f, A = 0.f;
#pragma unroll
        for (int w = 0; w < 8; w++) {
            float e = __expf(sm[g][w] - M);
            L += sl[g][w] * e;
            A += sa[g][w][d] * e;
        }
        int head = (b * NKVH + h) * 2 + g;
        int pi = head * NCHUNK + chunk;
        if (d == 0) { g_pm[pi] = M; g_pl[pi] = L; }
        g_pa[(size_t)pi * HD + d] = A;
    }
}

// ---------------- kernel 3: combine + output projection ---------------------
// grid 256: blk -> b = blk>>3, eblk = blk&7. 256 threads.
// Phase 1: combine partials -> sc[256] (per-CTA; 8x redundancy instead of 32x).
// Phase 2: warp w computes 4 outputs e = eblk*32 + w*4 + j.
__global__ void __launch_bounds__(256) outproj_kernel(
    const float* __restrict__ out_w, float* __restrict__ out)
{
    int blk = blockIdx.x;
    int b = blk >> 3, eblk = blk & 7;
    int t = threadIdx.x;
    __shared__ float sc[HIDDEN];

    {   // phase 1: combine chunk partials -> ctx[b][t]
        int g = t >> 6, d = t & 63;
        int head = b * NQH + g;
        float M = -1e30f;
#pragma unroll
        for (int c = 0; c < NCHUNK; c++) M = fmaxf(M, g_pm[head * NCHUNK + c]);
        float L = 0.f, A = 0.f;
#pragma unroll
        for (int c = 0; c < NCHUNK; c++) {
            float e = __expf(g_pm[head * NCHUNK + c] - M);
            L += g_pl[head * NCHUNK + c] * e;
            A += g_pa[(size_t)(head * NCHUNK + c) * HD + d] * e;
        }
        sc[t] = A / L;
    }
    __syncthreads();

    // phase 2: warp w -> outputs e = eblk*32 + w*4 + j, j=0..3
    int w = t >> 5, lane = t & 31;
    int e0 = eblk * 32 + w * 4;
    const float4* c4 = (const float4*)sc + lane * 2;
    float4 ca = c4[0], cb = c4[1];
    float s[4];
#pragma unroll
    for (int j = 0; j < 4; j++) {
        const float4* w4p = (const float4*)(out_w + (size_t)(e0 + j) * HIDDEN) + lane * 2;
        s[j] = dot4(w4p[0], ca) + dot4(w4p[1], cb);
    }
#pragma unroll
    for (int sft = 16; sft > 0; sft >>= 1) {
#pragma unroll
        for (int j = 0; j < 4; j++)
            s[j] += __shfl_xor_sync(0xffffffffu, s[j], sft);
    }
    if (lane == 0) {
#pragma unroll
        for (int j = 0; j < 4; j++)
            out[b * HIDDEN + e0 + j] = s[j];
    }
}

// ---------------- launch ----------------------------------------------------
extern "C" void kernel_launch(void* const* d_in, const int* in_sizes, int n_in,
                              void* d_out, int out_size)
{
    const float* x     = (const float*)d_in[0];
    const float* kv    = (const float*)d_in[1];
    const int*   ctx   = (const int*)d_in[2];
    const float* rope  = (const float*)d_in[3];
    const float* qkv_w = (const float*)d_in[4];
    const float* qkv_b = (const float*)d_in[5];
    const float* out_w = (const float*)d_in[6];
    float* out = (float*)d_out;

    qkv_rope_kernel<<<256, 256>>>(x, ctx, rope, qkv_w, qkv_b);
    fused_attn_copy<<<NB * NKVH * NCHUNK, 256>>>(kv, ctx, out);
    outproj_kernel<<<256, 256>>>(out_w, out);
}

// round 9
// speedup vs baseline: 1.3378x; 1.0127x over previous
#include <cuda_runtime.h>

#define NB 32
#define HIDDEN 256
#define NQH 4
#define NKVH 2
#define HD 64
#define QKV_DIM 512
#define MAXS 8192
#define CHUNK 256
#define NCHUNK (MAXS / CHUNK)          // 32
#define NHEAD (NB * NQH)               // 128

// ---------------- scratch (device globals) ----------------------------------
__device__ float g_q[NB * HIDDEN];
__device__ float g_k[NB * NKVH * HD];
__device__ float g_v[NB * NKVH * HD];
__device__ float g_pm[NHEAD * NCHUNK];
__device__ float g_pl[NHEAD * NCHUNK];
__device__ float g_pa[NHEAD * NCHUNK * HD];

__device__ __forceinline__ float dot4(float4 a, float4 b) {
    return a.x * b.x + a.y * b.y + a.z * b.z + a.w * b.w;
}

// ---------------- kernel 1: qkv projection + rope, warp-per-rope-pair -------
// (R7 exact: 8192 warps, chain depth 1, measured 6.2us)
__global__ void __launch_bounds__(256) qkv_rope_kernel(
    const float* __restrict__ x, const int* __restrict__ ctx_len,
    const float* __restrict__ rope, const float* __restrict__ qkv_w,
    const float* __restrict__ qkv_b)
{
    int W    = blockIdx.x * 8 + (threadIdx.x >> 5);
    int lane = threadIdx.x & 31;
    int b    = W & 31;
    int d    = (W >> 5) & 31;
    int hid  = W >> 10;                   // 0..7
    int elo  = hid * HD + d;
    int ehi  = elo + 32;

    const float4* wlo = (const float4*)(qkv_w + (size_t)elo * HIDDEN) + lane * 2;
    const float4* whi = (const float4*)(qkv_w + (size_t)ehi * HIDDEN) + lane * 2;
    const float4* xb  = (const float4*)(x + (size_t)b * HIDDEN) + lane * 2;

    float4 wl0 = wlo[0], wl1 = wlo[1];
    float4 wh0 = whi[0], wh1 = whi[1];
    float4 x0  = xb[0],  x1  = xb[1];

    float slo = dot4(wl0, x0) + dot4(wl1, x1);
    float shi = dot4(wh0, x0) + dot4(wh1, x1);
#pragma unroll
    for (int s = 16; s > 0; s >>= 1) {
        slo += __shfl_xor_sync(0xffffffffu, slo, s);
        shi += __shfl_xor_sync(0xffffffffu, shi, s);
    }

    if (lane == 0) {
        slo += qkv_b[elo];
        shi += qkv_b[ehi];
        float vlo, vhi;
        if (hid < NQH + NKVH) {           // q or k: rope
            int pos = ctx_len[b];
            float c = rope[(size_t)pos * HD + d];
            float s = rope[(size_t)pos * HD + 32 + d];
            vlo = slo * c - shi * s;
            vhi = slo * s + shi * c;
        } else {
            vlo = slo; vhi = shi;
        }
        if (hid < NQH) {
            g_q[b * HIDDEN + hid * HD + d]      = vlo;
            g_q[b * HIDDEN + hid * HD + d + 32] = vhi;
        } else if (hid < NQH + NKVH) {
            int hk = hid - NQH;
            g_k[(b * NKVH + hk) * HD + d]      = vlo;
            g_k[(b * NKVH + hk) * HD + d + 32] = vhi;
        } else {
            int hv = hid - NQH - NKVH;
            g_v[(b * NKVH + hv) * HD + d]      = vlo;
            g_v[(b * NKVH + hv) * HD + d + 32] = vhi;
        }
    }
}

// ---------------- kernel 2: fused KV-cache copy + flash-decode partials -----
// 2048 CTAs x 256 threads. Each CTA: 256 rows. Half-warp = one 64-float row.
__global__ void __launch_bounds__(256) fused_attn_copy(
    const float* __restrict__ kv, const int* __restrict__ ctx_len,
    float* __restrict__ out)
{
    int blk   = blockIdx.x;
    int chunk = blk & (NCHUNK - 1);
    int h     = (blk >> 5) & (NKVH - 1);
    int b     = blk >> 6;
    int warp  = threadIdx.x >> 5, lane = threadIdx.x & 31;
    int half  = lane >> 4, li = lane & 15;
    int pos   = ctx_len[b];

    size_t kb = (((size_t)b * 2 + 0) * NKVH + h) * (size_t)(MAXS * HD);
    size_t vb = kb + (size_t)NKVH * MAXS * HD;
    const float4* kp4 = (const float4*)(kv + kb);
    const float4* vp4 = (const float4*)(kv + vb);
    float4* okp4 = (float4*)(out + NB * HIDDEN + kb);
    float4* ovp4 = (float4*)(out + NB * HIDDEN + vb);

    int hq = h * 2;
    int d4 = li * 4;
    float4 q0 = *(const float4*)&g_q[((size_t)b * NQH + hq)     * HD + d4];
    float4 q1 = *(const float4*)&g_q[((size_t)b * NQH + hq + 1) * HD + d4];
    float4 kn = *(const float4*)&g_k[((size_t)b * NKVH + h) * HD + d4];
    float4 vn = *(const float4*)&g_v[((size_t)b * NKVH + h) * HD + d4];

    float m0 = -1e30f, l0 = 0.f, m1 = -1e30f, l1 = 0.f;
    float4 a0 = make_float4(0.f, 0.f, 0.f, 0.f);
    float4 a1 = make_float4(0.f, 0.f, 0.f, 0.f);
    const float scale = 0.125f;   // 64^-0.5

    int row0 = chunk * CHUNK + warp * (CHUNK / 8);
#pragma unroll 8
    for (int i = 0; i < CHUNK / 16; i++) {          // 2 rows per iter
        int m = row0 + 2 * i + half;                // per-half row
        size_t o4 = (size_t)m * (HD / 4) + li;
        float4 kd, vd;
        if (m == pos) { kd = kn; vd = vn; }
        else          { kd = __ldcs(kp4 + o4); vd = __ldcs(vp4 + o4); }
        __stcs(okp4 + o4, kd);
        __stcs(ovp4 + o4, vd);

        if (row0 + 2 * i <= pos) {                  // warp-uniform guard
            float p0 = kd.x * q0.x + kd.y * q0.y + kd.z * q0.z + kd.w * q0.w;
            float p1 = kd.x * q1.x + kd.y * q1.y + kd.z * q1.z + kd.w * q1.w;
#pragma unroll
            for (int sft = 8; sft > 0; sft >>= 1) { // stays within 16-lane half
                p0 += __shfl_xor_sync(0xffffffffu, p0, sft);
                p1 += __shfl_xor_sync(0xffffffffu, p1, sft);
            }
            if (m <= pos) {                          // per-half, ALU only
                p0 *= scale; p1 *= scale;
                float nm0 = fmaxf(m0, p0), nm1 = fmaxf(m1, p1);
                float f0 = __expf(m0 - nm0), w0 = __expf(p0 - nm0);
                float f1 = __expf(m1 - nm1), w1 = __expf(p1 - nm1);
                l0 = l0 * f0 + w0;  l1 = l1 * f1 + w1;
                a0.x = a0.x * f0 + w0 * vd.x;  a0.y = a0.y * f0 + w0 * vd.y;
                a0.z = a0.z * f0 + w0 * vd.z;  a0.w = a0.w * f0 + w0 * vd.w;
                a1.x = a1.x * f1 + w1 * vd.x;  a1.y = a1.y * f1 + w1 * vd.y;
                a1.z = a1.z * f1 + w1 * vd.z;  a1.w = a1.w * f1 + w1 * vd.w;
                m0 = nm0; m1 = nm1;
            }
        }
    }

    // merge the two half-warp softmax streams per head (shfl_xor 16)
    {
        float mo = __shfl_xor_sync(0xffffffffu, m0, 16);
        float lo = __shfl_xor_sync(0xffffffffu, l0, 16);
        float4 ao;
        ao.x = __shfl_xor_sync(0xffffffffu, a0.x, 16);
        ao.y = __shfl_xor_sync(0xffffffffu, a0.y, 16);
        ao.z = __shfl_xor_sync(0xffffffffu, a0.z, 16);
        ao.w = __shfl_xor_sync(0xffffffffu, a0.w, 16);
        float M = fmaxf(m0, mo);
        float e0 = __expf(m0 - M), e1 = __expf(mo - M);
        l0 = l0 * e0 + lo * e1;
        a0.x = a0.x * e0 + ao.x * e1;  a0.y = a0.y * e0 + ao.y * e1;
        a0.z = a0.z * e0 + ao.z * e1;  a0.w = a0.w * e0 + ao.w * e1;
        m0 = M;
    }
    {
        float mo = __shfl_xor_sync(0xffffffffu, m1, 16);
        float lo = __shfl_xor_sync(0xffffffffu, l1, 16);
        float4 ao;
        ao.x = __shfl_xor_sync(0xffffffffu, a1.x, 16);
        ao.y = __shfl_xor_sync(0xffffffffu, a1.y, 16);
        ao.z = __shfl_xor_sync(0xffffffffu, a1.z, 16);
        ao.w = __shfl_xor_sync(0xffffffffu, a1.w, 16);
        float M = fmaxf(m1, mo);
        float e0 = __expf(m1 - M), e1 = __expf(mo - M);
        l1 = l1 * e0 + lo * e1;
        a1.x = a1.x * e0 + ao.x * e1;  a1.y = a1.y * e0 + ao.y * e1;
        a1.z = a1.z * e0 + ao.z * e1;  a1.w = a1.w * e0 + ao.w * e1;
        m1 = M;
    }

    // cross-warp combine
    __shared__ float sm[2][8], sl[2][8], sa[2][8][HD];
    if (lane == 0) { sm[0][warp] = m0; sl[0][warp] = l0; sm[1][warp] = m1; sl[1][warp] = l1; }
    if (half == 0) {
        *(float4*)&sa[0][warp][d4] = a0;
        *(float4*)&sa[1][warp][d4] = a1;
    }
    __syncthreads();

    int t = threadIdx.x;
    if (t < 128) {
        int g = t >> 6, d = t & 63;
        float M = -1e30f;
#pragma unroll
        for (int w = 0; w < 8; w++) M = fmaxf(M, sm[g][w]);
        float L = 0.f, A = 0.f;
#pragma unroll
        for (int w = 0; w < 8; w++) {
            float e = __expf(sm[g][w] - M);
            L += sl[g][w] * e;
            A += sa[g][w][d] * e;
        }
        int head = (b * NKVH + h) * 2 + g;
        int pi = head * NCHUNK + chunk;
        if (d == 0) { g_pm[pi] = M; g_pl[pi] = L; }
        g_pa[(size_t)pi * HD + d] = A;
    }
}

// ---------------- kernel 3: combine + output projection ---------------------
// grid 256: blk -> b = blk>>3, eblk = blk&7. 256 threads.
__global__ void __launch_bounds__(256) outproj_kernel(
    const float* __restrict__ out_w, float* __restrict__ out)
{
    int blk = blockIdx.x;
    int b = blk >> 3, eblk = blk & 7;
    int t = threadIdx.x;
    __shared__ float sc[HIDDEN];

    {   // phase 1: combine chunk partials -> ctx[b][t]
        int g = t >> 6, d = t & 63;
        int head = b * NQH + g;
        float M = -1e30f;
#pragma unroll
        for (int c = 0; c < NCHUNK; c++) M = fmaxf(M, g_pm[head * NCHUNK + c]);
        float L = 0.f, A = 0.f;
#pragma unroll
        for (int c = 0; c < NCHUNK; c++) {
            float e = __expf(g_pm[head * NCHUNK + c] - M);
            L += g_pl[head * NCHUNK + c] * e;
            A += g_pa[(size_t)(head * NCHUNK + c) * HD + d] * e;
        }
        sc[t] = A / L;
    }
    __syncthreads();

    // phase 2: warp w -> outputs e = eblk*32 + w*4 + j, j=0..3
    int w = t >> 5, lane = t & 31;
    int e0 = eblk * 32 + w * 4;
    const float4* c4 = (const float4*)sc + lane * 2;
    float4 ca = c4[0], cb = c4[1];
    float s[4];
#pragma unroll
    for (int j = 0; j < 4; j++) {
        const float4* w4p = (const float4*)(out_w + (size_t)(e0 + j) * HIDDEN) + lane * 2;
        s[j] = dot4(w4p[0], ca) + dot4(w4p[1], cb);
    }
#pragma unroll
    for (int sft = 16; sft > 0; sft >>= 1) {
#pragma unroll
        for (int j = 0; j < 4; j++)
            s[j] += __shfl_xor_sync(0xffffffffu, s[j], sft);
    }
    if (lane == 0) {
#pragma unroll
        for (int j = 0; j < 4; j++)
            out[b * HIDDEN + e0 + j] = s[j];
    }
}

// ---------------- launch ----------------------------------------------------
extern "C" void kernel_launch(void* const* d_in, const int* in_sizes, int n_in,
                              void* d_out, int out_size)
{
    const float* x     = (const float*)d_in[0];
    const float* kv    = (const float*)d_in[1];
    const int*   ctx   = (const int*)d_in[2];
    const float* rope  = (const float*)d_in[3];
    const float* qkv_w = (const float*)d_in[4];
    const float* qkv_b = (const float*)d_in[5];
    const float* out_w = (const float*)d_in[6];
    float* out = (float*)d_out;

    qkv_rope_kernel<<<1024, 256>>>(x, ctx, rope, qkv_w, qkv_b);
    fused_attn_copy<<<NB * NKVH * NCHUNK, 256>>>(kv, ctx, out);
    outproj_kernel<<<256, 256>>>(out_w, out);
}